// round 9
// baseline (speedup 1.0000x reference)
#include <cuda_runtime.h>
#include <cuda_fp16.h>

#define NN 100000
#define NE 1280000
#define FD 64
#define NG 1000
#define BN_EPS 1e-5f
#define SCAN_CH 1024
#define SCAN_NB ((NN + SCAN_CH - 1) / SCAN_CH)   // 98
#define TROWS 48
#define NT ((NN + TROWS - 1) / TROWS)            // 2084
#define GEMM_BLOCKS 592

// ---------------- device scratch (allocation-free rule: __device__ globals) ----
__device__ int    g_deg[NN];
__device__ float  g_dinv[NN];
__device__ __half g_th[(size_t)NN * FD];      // transformed features (fp16 messages)
__device__ float  g_agg[(size_t)NN * FD];     // aggregated features (fp32)
__device__ float  g_stats[6 * FD];            // s1 ss1 | s2 ss2 | s3 ss3
__device__ float  g_gsum[NG * FD];
__device__ float  g_gcnt[NG];
__device__ int    g_is64;
// CSR sorted by destination; packed (src, norm-bits)
__device__ int    g_rowptr[NN + 1];
__device__ int    g_fill[NN];
__device__ int2   g_csr[NE];
__device__ int    g_bsum[SCAN_NB];
__device__ int    g_boff[SCAN_NB];

__device__ __forceinline__ unsigned pack_half2(float a, float b) {
    __half2 h = __floats2half2_rn(a, b);
    return (unsigned)__half_as_ushort(__low2half(h)) |
           ((unsigned)__half_as_ushort(__high2half(h)) << 16);
}

// ---------------- init + dtype detect (block 0 detects int64 via odd words==0)
__global__ void init_kernel(const int* __restrict__ ei) {
    int i = blockIdx.x * blockDim.x + threadIdx.x;
    if (i < NN) g_deg[i] = 0;
    if (i < 6 * FD) g_stats[i] = 0.0f;
    if (i < NG * FD) g_gsum[i] = 0.0f;
    if (i < NG) g_gcnt[i] = 0.0f;
    if (blockIdx.x == 0) {
        __shared__ int nz;
        if (threadIdx.x == 0) nz = 0;
        __syncthreads();
        int local = 0;
        for (int k = threadIdx.x; k < 4096; k += blockDim.x)
            if (ei[2 * k + 1] != 0) local = 1;
        if (local) nz = 1;
        __syncthreads();
        if (threadIdx.x == 0) g_is64 = (nz == 0) ? 1 : 0;
    }
}

__global__ void deg_kernel(const int* __restrict__ ei) {
    int e = blockIdx.x * blockDim.x + threadIdx.x;
    if (e >= NE) return;
    int c = g_is64 ? ei[2 * (NE + e)] : ei[NE + e];
    atomicAdd(&g_deg[c], 1);
}

// ---------------- rsqrt(deg+1) + per-chunk sums (scan level A) --------------
__global__ void rsqrt_scanA_kernel() {
    __shared__ int sh[256];
    int b = blockIdx.x, t = threadIdx.x;
    int base = b * SCAN_CH + t * 4;
    int s = 0;
#pragma unroll
    for (int k = 0; k < 4; k++) {
        int i = base + k;
        if (i < NN) {
            int d = g_deg[i];
            g_dinv[i] = rsqrtf((float)d + 1.0f);
            s += d;
        }
    }
    sh[t] = s;
    __syncthreads();
    for (int off = 128; off > 0; off >>= 1) {
        if (t < off) sh[t] += sh[t + off];
        __syncthreads();
    }
    if (t == 0) g_bsum[b] = sh[0];
}

__global__ void scanB_kernel() {
    if (threadIdx.x == 0) {
        int acc = 0;
        for (int b = 0; b < SCAN_NB; b++) { g_boff[b] = acc; acc += g_bsum[b]; }
        g_rowptr[NN] = acc;
    }
}

__global__ void scanC_kernel() {
    __shared__ int sh[257];
    int b = blockIdx.x, t = threadIdx.x;
    int base = b * SCAN_CH + t * 4;
    int v[4]; int s = 0;
#pragma unroll
    for (int k = 0; k < 4; k++) {
        int i = base + k;
        v[k] = (i < NN) ? g_deg[i] : 0;
        s += v[k];
    }
    sh[t + 1] = s;
    if (t == 0) sh[0] = 0;
    __syncthreads();
    for (int off = 1; off < 256; off <<= 1) {
        int val = (t + 1 > off) ? sh[t + 1 - off] : 0;
        __syncthreads();
        sh[t + 1] += val;
        __syncthreads();
    }
    int run = g_boff[b] + sh[t];
#pragma unroll
    for (int k = 0; k < 4; k++) {
        int i = base + k;
        if (i < NN) { g_rowptr[i] = run; g_fill[i] = run; run += v[k]; }
    }
}

__global__ void place_kernel(const int* __restrict__ ei) {
    int e = blockIdx.x * blockDim.x + threadIdx.x;
    if (e >= NE) return;
    int r, c;
    if (g_is64) { r = ei[2 * e]; c = ei[2 * (NE + e)]; }
    else        { r = ei[e];     c = ei[NE + e]; }
    int pos = atomicAdd(&g_fill[c], 1);
    float nrm = g_dinv[r] * g_dinv[c];
    g_csr[pos] = make_int2(r, __float_as_int(nrm));
}

// ---------------- BN stats for layer-1 input x ------------------------------
__global__ void bn_stats_x_kernel(const float* __restrict__ x) {
    int f   = threadIdx.x & 63;
    int sub = threadIdx.x >> 6;
    float s = 0.0f, ss = 0.0f;
    for (int n = blockIdx.x * 4 + sub; n < NN; n += gridDim.x * 4) {
        float v = x[(size_t)n * FD + f];
        s += v; ss += v * v;
    }
    atomicAdd(&g_stats[f], s);
    atomicAdd(&g_stats[64 + f], ss);
}

// ---------------- persistent, double-buffered GEMM with fused BN fold --------
//   t = prologue(in) @ (diag(a)W) + c@W    (prologue = relu(in+bias) if dorelu)
// Each block folds W ONCE, then loops 48-row tiles with next-tile global loads
// issued into registers before computing the current tile (latency hidden).
__global__ void gemm_kernel(const float* __restrict__ xin, int use_agg,
                            const float* __restrict__ bias, int dorelu,
                            const float* __restrict__ gg, const float* __restrict__ bb,
                            const float* __restrict__ W, int soff) {
    __shared__ float sW[FD * FD];
    __shared__ float sIn[2][TROWS * 68];    // 2 x 12.75KB, float4-aligned rows
    __shared__ float sA[FD], sC[FD], sCrow[FD], sBias[FD];
    const float* __restrict__ src = use_agg ? g_agg : xin;
    int tid = threadIdx.x;

    // one-time: raw W, fold coefficients, crow, scale
    for (int i = tid; i < FD * FD; i += 256) sW[i] = W[i];
    if (tid < FD) {
        float m = g_stats[soff + tid] * (1.0f / NN);
        float v = fmaxf(g_stats[soff + 64 + tid] * (1.0f / NN) - m * m, 0.0f);
        float af = gg[tid] * rsqrtf(v + BN_EPS);
        sA[tid] = af;
        sC[tid] = bb[tid] - m * af;
        sBias[tid] = dorelu ? bias[tid] : 0.0f;
    }
    __syncthreads();
    float cr = 0.0f;
    if (tid < FD) {
        for (int i = 0; i < FD; i++) cr += sC[i] * sW[i * FD + tid];
    }
    __syncthreads();
    for (int i = tid; i < FD * FD; i += 256) sW[i] *= sA[i >> 6];
    if (tid < FD) sCrow[tid] = cr;

    const float4* src4 = (const float4*)src;
    int lr[3], lc[3];
#pragma unroll
    for (int k = 0; k < 3; k++) {
        int i = tid + k * 256;
        lr[k] = i >> 4;               // row in tile (0..47)
        lc[k] = i & 15;               // float4 column (0..15)
    }

    // prefetch first tile
    int t = blockIdx.x;
    float4 pf[3];
    {
        int base = t * TROWS;
#pragma unroll
        for (int k = 0; k < 3; k++) {
            int node = base + lr[k];
            float4 v = make_float4(0.f, 0.f, 0.f, 0.f);
            if (node < NN) {
                v = src4[(size_t)node * 16 + lc[k]];
                if (dorelu) {
                    float4 bv = ((const float4*)sBias)[lc[k]];
                    v.x = fmaxf(v.x + bv.x, 0.0f);
                    v.y = fmaxf(v.y + bv.y, 0.0f);
                    v.z = fmaxf(v.z + bv.z, 0.0f);
                    v.w = fmaxf(v.w + bv.w, 0.0f);
                }
            }
            pf[k] = v;
        }
    }
    int buf = 0;
#pragma unroll
    for (int k = 0; k < 3; k++)
        *((float4*)&sIn[buf][lr[k] * 68 + lc[k] * 4]) = pf[k];
    __syncthreads();

    int rp = tid >> 4, tc = tid & 15;
    int rbase = rp * 3;
    const float4* sW4 = (const float4*)sW;
    float4 crw = ((const float4*)sCrow)[tc];
    uint2* th2 = (uint2*)g_th;

    for (; t < NT; t += GEMM_BLOCKS) {
        int tn = t + GEMM_BLOCKS;
        // issue next tile's loads (registers) before compute
        if (tn < NT) {
            int base2 = tn * TROWS;
#pragma unroll
            for (int k = 0; k < 3; k++) {
                int node = base2 + lr[k];
                float4 v = make_float4(0.f, 0.f, 0.f, 0.f);
                if (node < NN) {
                    v = src4[(size_t)node * 16 + lc[k]];
                    if (dorelu) {
                        float4 bv = ((const float4*)sBias)[lc[k]];
                        v.x = fmaxf(v.x + bv.x, 0.0f);
                        v.y = fmaxf(v.y + bv.y, 0.0f);
                        v.z = fmaxf(v.z + bv.z, 0.0f);
                        v.w = fmaxf(v.w + bv.w, 0.0f);
                    }
                }
                pf[k] = v;
            }
        }

        // compute current tile: 3 rows x 4 cols per thread
        const float* in = &sIn[buf][rbase * 68];
        float4 acc0 = make_float4(0.f, 0.f, 0.f, 0.f);
        float4 acc1 = make_float4(0.f, 0.f, 0.f, 0.f);
        float4 acc2 = make_float4(0.f, 0.f, 0.f, 0.f);
#pragma unroll
        for (int k4 = 0; k4 < 16; k4++) {
            float4 x0 = *(const float4*)&in[0 * 68 + k4 * 4];
            float4 x1 = *(const float4*)&in[1 * 68 + k4 * 4];
            float4 x2 = *(const float4*)&in[2 * 68 + k4 * 4];
#pragma unroll
            for (int kk = 0; kk < 4; kk++) {
                float4 w = sW4[(k4 * 4 + kk) * 16 + tc];
                float v0 = kk == 0 ? x0.x : kk == 1 ? x0.y : kk == 2 ? x0.z : x0.w;
                float v1 = kk == 0 ? x1.x : kk == 1 ? x1.y : kk == 2 ? x1.z : x1.w;
                float v2 = kk == 0 ? x2.x : kk == 1 ? x2.y : kk == 2 ? x2.z : x2.w;
                acc0.x += v0 * w.x; acc0.y += v0 * w.y; acc0.z += v0 * w.z; acc0.w += v0 * w.w;
                acc1.x += v1 * w.x; acc1.y += v1 * w.y; acc1.z += v1 * w.z; acc1.w += v1 * w.w;
                acc2.x += v2 * w.x; acc2.y += v2 * w.y; acc2.z += v2 * w.z; acc2.w += v2 * w.w;
            }
        }
        acc0.x += crw.x; acc0.y += crw.y; acc0.z += crw.z; acc0.w += crw.w;
        acc1.x += crw.x; acc1.y += crw.y; acc1.z += crw.z; acc1.w += crw.w;
        acc2.x += crw.x; acc2.y += crw.y; acc2.z += crw.z; acc2.w += crw.w;

        int base = t * TROWS;
        int n0 = base + rbase;
        if (n0 < NN)     th2[(size_t)n0 * 16 + tc]       = make_uint2(pack_half2(acc0.x, acc0.y), pack_half2(acc0.z, acc0.w));
        if (n0 + 1 < NN) th2[(size_t)(n0 + 1) * 16 + tc] = make_uint2(pack_half2(acc1.x, acc1.y), pack_half2(acc1.z, acc1.w));
        if (n0 + 2 < NN) th2[(size_t)(n0 + 2) * 16 + tc] = make_uint2(pack_half2(acc2.x, acc2.y), pack_half2(acc2.z, acc2.w));

        // stage next tile into the other buffer
        if (tn < NT) {
#pragma unroll
            for (int k = 0; k < 3; k++)
                *((float4*)&sIn[buf ^ 1][lr[k] * 68 + lc[k] * 4]) = pf[k];
        }
        __syncthreads();
        buf ^= 1;
    }
}

// ---------------- CSR gather conv: warp/node, lane = 2 feats, fp16 messages.
// CSR read as int4 (2 edges per load) with odd-start peel.
// Optional epilogue: BN stats of relu(agg + bias) via block reduction.
__global__ void gather_kernel(int do_stats, const float* __restrict__ bias, int soff) {
    __shared__ float sStat[128];
    int tid  = threadIdx.x;
    int lane = tid & 31;
    if (do_stats && tid < 128) sStat[tid] = 0.0f;

    int n = (blockIdx.x * blockDim.x + tid) >> 5;   // 16 nodes per 512-thread block
    const __half2* th2 = (const __half2*)g_th;
    float d = g_dinv[n];
    float s = d * d;
    float2 acc = __half22float2(th2[(size_t)n * 32 + lane]);
    acc.x *= s; acc.y *= s;

    int j = g_rowptr[n], end = g_rowptr[n + 1];
    if (j < end && (j & 1)) {
        int2 p = g_csr[j];
        float2 v = __half22float2(th2[(size_t)p.x * 32 + lane]);
        float w = __int_as_float(p.y);
        acc.x += v.x * w; acc.y += v.y * w;
        j++;
    }
    const int4* csr4 = (const int4*)g_csr;
    for (; j + 2 <= end; j += 2) {
        int4 p = csr4[j >> 1];
        float2 v0 = __half22float2(th2[(size_t)p.x * 32 + lane]);
        float2 v1 = __half22float2(th2[(size_t)p.z * 32 + lane]);
        float w0 = __int_as_float(p.y), w1 = __int_as_float(p.w);
        acc.x += v0.x * w0 + v1.x * w1;
        acc.y += v0.y * w0 + v1.y * w1;
    }
    if (j < end) {
        int2 p = g_csr[j];
        float2 v = __half22float2(th2[(size_t)p.x * 32 + lane]);
        float w = __int_as_float(p.y);
        acc.x += v.x * w; acc.y += v.y * w;
    }
    ((float2*)g_agg)[(size_t)n * 32 + lane] = acc;

    if (do_stats) {
        float2 bb = ((const float2*)bias)[lane];
        float y0 = fmaxf(acc.x + bb.x, 0.0f);
        float y1 = fmaxf(acc.y + bb.y, 0.0f);
        __syncthreads();             // zero-fill visible, all accs done
        atomicAdd(&sStat[2 * lane],      y0);
        atomicAdd(&sStat[2 * lane + 1],  y1);
        atomicAdd(&sStat[64 + 2 * lane],     y0 * y0);
        atomicAdd(&sStat[64 + 2 * lane + 1], y1 * y1);
        __syncthreads();
        if (tid < 128) atomicAdd(&g_stats[soff + tid], sStat[tid]);
    }
}

// ---------------- pool: y=relu(agg+b2); BN3 stats + per-graph sums (batch sorted)
__global__ void pool_kernel(const float* __restrict__ bias, const int* __restrict__ batch) {
    int f   = threadIdx.x & 63;
    int sub = threadIdx.x >> 6;
    int is64 = g_is64;
    float bs = bias[f];
    const int chunk = 196;                 // 512 blocks * 196 >= NN
    const int subc  = 49;
    int start = blockIdx.x * chunk + sub * subc;
    int stop  = min(start + subc, NN);
    float s = 0.0f, ss = 0.0f;
    int   cur = -1;
    float gv = 0.0f, gc = 0.0f;
    for (int n = start; n < stop; n++) {
        int b = is64 ? batch[2 * n] : batch[n];
        if (b != cur) {
            if (cur >= 0) {
                atomicAdd(&g_gsum[cur * FD + f], gv);
                if (f == 0) atomicAdd(&g_gcnt[cur], gc);
            }
            cur = b; gv = 0.0f; gc = 0.0f;
        }
        float v = fmaxf(g_agg[(size_t)n * FD + f] + bs, 0.0f);
        s += v; ss += v * v;
        gv += v; gc += 1.0f;
    }
    if (cur >= 0) {
        atomicAdd(&g_gsum[cur * FD + f], gv);
        if (f == 0) atomicAdd(&g_gcnt[cur], gc);
    }
    atomicAdd(&g_stats[256 + f], s);
    atomicAdd(&g_stats[320 + f], ss);
}

// ---------------- final: fold BN3 into Wout, emit [NG, 2] --------------------
__global__ void final_kernel(const float* __restrict__ gg, const float* __restrict__ bb,
                             const float* __restrict__ Wout, const float* __restrict__ bout,
                             float* __restrict__ out) {
    __shared__ float sWp[FD * 2];
    __shared__ float sc[FD];
    __shared__ float scb[2];
    int tid = threadIdx.x;
    if (tid < FD) {
        float m = g_stats[256 + tid] * (1.0f / NN);
        float v = fmaxf(g_stats[320 + tid] * (1.0f / NN) - m * m, 0.0f);
        float af = gg[tid] * rsqrtf(v + BN_EPS);
        sc[tid] = bb[tid] - m * af;
        sWp[tid * 2]     = af * Wout[tid * 2];
        sWp[tid * 2 + 1] = af * Wout[tid * 2 + 1];
    }
    __syncthreads();
    if (tid < 2) {
        float acc = bout[tid];
        for (int i = 0; i < FD; i++) acc += sc[i] * Wout[i * 2 + tid];
        scb[tid] = acc;
    }
    __syncthreads();
    int g = blockIdx.x * blockDim.x + tid;
    if (g >= NG) return;
    float cnt = g_gcnt[g];
    if (cnt > 0.0f) {
        float inv = 1.0f / cnt;
        float a0 = scb[0], a1 = scb[1];
#pragma unroll 8
        for (int f = 0; f < FD; f++) {
            float p = g_gsum[g * FD + f] * inv;
            a0 += p * sWp[f * 2];
            a1 += p * sWp[f * 2 + 1];
        }
        out[g * 2] = a0; out[g * 2 + 1] = a1;
    } else {
        out[g * 2] = bout[0]; out[g * 2 + 1] = bout[1];
    }
}

extern "C" void kernel_launch(void* const* d_in, const int* in_sizes, int n_in,
                              void* d_out, int out_size) {
    const float* x       = (const float*)d_in[0];
    const int*   ei      = (const int*)d_in[1];
    const int*   batch   = (const int*)d_in[2];
    const float* bn_in_g = (const float*)d_in[3];
    const float* bn_in_b = (const float*)d_in[4];
    const float* W1      = (const float*)d_in[5];
    const float* b1      = (const float*)d_in[6];
    const float* g1      = (const float*)d_in[7];
    const float* be1     = (const float*)d_in[8];
    const float* W2      = (const float*)d_in[9];
    const float* b2      = (const float*)d_in[10];
    const float* g2      = (const float*)d_in[11];
    const float* be2     = (const float*)d_in[12];
    const float* Wout    = (const float*)d_in[13];
    const float* bout    = (const float*)d_in[14];
    float* out = (float*)d_out;

    init_kernel<<<(NN + 255) / 256, 256>>>(ei);
    deg_kernel<<<(NE + 255) / 256, 256>>>(ei);
    bn_stats_x_kernel<<<512, 256>>>(x);
    gemm_kernel<<<GEMM_BLOCKS, 256>>>(x, 0, x, 0, bn_in_g, bn_in_b, W1, 0); // conv1 transform
    rsqrt_scanA_kernel<<<SCAN_NB, 256>>>();
    scanB_kernel<<<1, 32>>>();
    scanC_kernel<<<SCAN_NB, 256>>>();
    place_kernel<<<(NE + 255) / 256, 256>>>(ei);
    gather_kernel<<<NN / 16, 512>>>(1, b1, 128);                            // conv1 agg + BN2 stats
    gemm_kernel<<<GEMM_BLOCKS, 256>>>(x, 1, b1, 1, g1, be1, W2, 128);       // conv2 transform
    gather_kernel<<<NN / 16, 512>>>(0, b1, 0);                              // conv2 agg
    pool_kernel<<<512, 256>>>(b2, batch);
    final_kernel<<<4, 256>>>(g2, be2, Wout, bout, out);
}